// round 15
// baseline (speedup 1.0000x reference)
#include <cuda_runtime.h>
#include <cuda_bf16.h>
#include <math.h>
#include <stdint.h>

// Problem dims
#define NB 8
#define CC 512
#define SS 4096     // N = H*W tokens
#define HD 2048     // HID = 4*C
#define HH 64

#define STAGES 4
#define KCHUNK 16   // column-softmax chunks

#define QKS (3LL*CC*SS)   // per-batch stride of the merged qkv buffer

// ---------------- scratch (device globals; no allocation allowed) ----------
__device__ float g_qkv[(long long)NB*3*CC*SS];   // 192MB: per batch [q|k|v]
__device__ float g_xr [(long long)NB*CC*SS];     // tf32-rounded x
__device__ float g_kt [(long long)NB*CC*SS];
__device__ float g_enh[(long long)NB*SS*CC];
__device__ float g_t  [(long long)NB*SS*CC];
__device__ float g_a  [(long long)NB*SS*HD];
__device__ float g_ax [(long long)NB*SS*HD];
__device__ float g_kv [(long long)NB*CC*CC];
__device__ float g_kvp[(long long)4*NB*CC*CC];   // split-K partials
__device__ float g_wqkv[3*CC*CC];                // stacked, tf32-rounded
__device__ float g_bqkv[3*CC];
__device__ float g_w1 [(long long)CC*HD];
__device__ float g_w2 [(long long)HD*CC];
__device__ float g_ksum[NB*CC];
__device__ float g_z  [NB*SS];
__device__ float g_cpm[NB*CC*KCHUNK];
__device__ float g_cps[NB*CC*KCHUNK];
__device__ float g_cfm[NB*CC];                   // per-col max
__device__ float g_cfa[NB*CC];                   // per-col inv*isc
__device__ float g_cfb[NB*CC];                   // per-col 1e-6*isc

// ---------------- helpers ---------------------------------------------------
__device__ __forceinline__ float blockReduceSum(float val) {
    __shared__ float sh[32];
    int lane = threadIdx.x & 31, wid = threadIdx.x >> 5;
    #pragma unroll
    for (int o = 16; o > 0; o >>= 1) val += __shfl_xor_sync(0xffffffff, val, o);
    if (lane == 0) sh[wid] = val;
    __syncthreads();
    float tot = 0.f;
    if (wid == 0) {
        tot = (lane < (int)(blockDim.x >> 5)) ? sh[lane] : 0.f;
        #pragma unroll
        for (int o = 16; o > 0; o >>= 1) tot += __shfl_xor_sync(0xffffffff, tot, o);
        if (lane == 0) sh[0] = tot;
    }
    __syncthreads();
    tot = sh[0];
    __syncthreads();
    return tot;
}

__device__ __forceinline__ float4 blockReduceSum4(float4 v) {
    __shared__ float4 sh[32];
    int lane = threadIdx.x & 31, wid = threadIdx.x >> 5;
    #pragma unroll
    for (int o = 16; o > 0; o >>= 1) {
        v.x += __shfl_xor_sync(0xffffffff, v.x, o);
        v.y += __shfl_xor_sync(0xffffffff, v.y, o);
        v.z += __shfl_xor_sync(0xffffffff, v.z, o);
        v.w += __shfl_xor_sync(0xffffffff, v.w, o);
    }
    if (lane == 0) sh[wid] = v;
    __syncthreads();
    float4 tot = make_float4(0.f, 0.f, 0.f, 0.f);
    if (wid == 0) {
        if (lane < (int)(blockDim.x >> 5)) tot = sh[lane];
        #pragma unroll
        for (int o = 16; o > 0; o >>= 1) {
            tot.x += __shfl_xor_sync(0xffffffff, tot.x, o);
            tot.y += __shfl_xor_sync(0xffffffff, tot.y, o);
            tot.z += __shfl_xor_sync(0xffffffff, tot.z, o);
            tot.w += __shfl_xor_sync(0xffffffff, tot.w, o);
        }
        if (lane == 0) sh[0] = tot;
    }
    __syncthreads();
    tot = sh[0];
    __syncthreads();
    return tot;
}

__device__ __forceinline__ float cvt_tf32(float v) {
    uint32_t u;
    asm("cvt.rna.tf32.f32 %0, %1;" : "=r"(u) : "f"(v));
    return __uint_as_float(u);
}

__device__ __forceinline__ void cp16(uint32_t s, const void* g) {
    asm volatile("cp.async.cg.shared.global [%0], [%1], 16;" :: "r"(s), "l"(g));
}

#define MMA_TF32(d, a, b) \
    asm volatile("mma.sync.aligned.m16n8k8.row.col.f32.tf32.tf32.f32 " \
        "{%0,%1,%2,%3},{%4,%5,%6,%7},{%8,%9},{%0,%1,%2,%3};" \
        : "+f"(d[0]), "+f"(d[1]), "+f"(d[2]), "+f"(d[3]) \
        : "r"(a[0]), "r"(a[1]), "r"(a[2]), "r"(a[3]), "r"(b[0]), "r"(b[1]))

#define LDMX4(dst, addr) \
    asm volatile("ldmatrix.sync.aligned.m8n8.x4.shared.b16 {%0,%1,%2,%3}, [%4];" \
        : "=r"(dst[0]), "=r"(dst[1]), "=r"(dst[2]), "=r"(dst[3]) : "r"(addr) : "memory")

#define AS_FLOATS (STAGES * 128 * 20)
#define BS_FLOATS (STAGES * 16 * 136)
#define SMEM_GEMM_BYTES ((AS_FLOATS + BS_FLOATS) * 4)
#define SMEM_SRKT (32 * 513 * 4)

// ---------------- single-pass TF32 GEMM, BK=16, 4-stage cp.async -----------
// All inputs pre-rounded to tf32.
// MODE: 0 = +bias[row]; 1 = plain; 2 = acc*z[row] + x^T tile (e1 = x, NCHW);
//       3 = +bias[col]; 4 = +bias[col]+res.  RND: tf32-round stores.
//       SPLITK: 4-way K split.
template<int MODE, bool CVTB, bool RND, bool SPLITK>
__global__ void __launch_bounds__(256, 2)
gemm_tc(const float* __restrict__ A, const float* __restrict__ B,
        float* __restrict__ C, int M, int N, int K,
        long long strA, long long strB, long long strC,
        const float* __restrict__ e0, const float* __restrict__ e1,
        long long strE0, long long strE1)
{
    extern __shared__ float smem[];
    float* Asm = smem;
    float* Bsm = smem + AS_FLOATS;

    int bz = blockIdx.z;
    int keff = K;
    if (SPLITK) {
        int slice = bz & 3;
        int batch = bz >> 2;
        A += (long long)batch * strA + slice * 1024;
        B += (long long)batch * strB + (long long)slice * 1024 * N;
        C += (long long)bz * strC;
        keff = 1024;
    } else {
        A += (long long)bz * strA;
        B += (long long)bz * strB;
        C += (long long)bz * strC;
    }
    const float* E0 = e0 ? e0 + (long long)bz * strE0 : nullptr;
    const float* E1 = e1 ? e1 + (long long)bz * strE1 : nullptr;

    const int t    = threadIdx.x;
    const int lane = t & 31, warp = t >> 5;
    const int m0   = blockIdx.y * 128, n0 = blockIdx.x * 128;
    const int wm0  = (warp & 1) * 64;
    const int wn0  = (warp >> 1) * 32;

    const int arow = t >> 1,  acol = (t & 1) * 8;
    const int brow = t >> 4,  bcol = (t & 15) * 8;

    const uint32_t sA = (uint32_t)__cvta_generic_to_shared(Asm);
    const uint32_t sB = (uint32_t)__cvta_generic_to_shared(Bsm);

    float acc[4][4][4];
    #pragma unroll
    for (int i = 0; i < 4; i++)
        #pragma unroll
        for (int j = 0; j < 4; j++)
            #pragma unroll
            for (int r = 0; r < 4; r++) acc[i][j][r] = 0.f;

    const int aRow    = wm0 + (lane & 15);
    const int aColSel = (lane >> 4) << 2;
    const int bkRow   = lane & 3;
    const int bnCol   = wn0 + (lane >> 2);

    const int nk = keff >> 4;

    auto load_stage = [&](int kt, int buf) {
        const float* ap = A + (long long)(m0 + arow) * K + (kt << 4) + acol;
        uint32_t sa = sA + (uint32_t)(((buf * 128 + arow) * 20 + acol) << 2);
        cp16(sa, ap);
        cp16(sa + 16, ap + 4);
        const float* bp = B + (long long)((kt << 4) + brow) * N + n0 + bcol;
        uint32_t sb = sB + (uint32_t)(((buf * 16 + brow) * 136 + bcol) << 2);
        cp16(sb, bp);
        cp16(sb + 16, bp + 4);
    };

    #pragma unroll
    for (int s = 0; s < STAGES - 1; s++) {
        if (s < nk) load_stage(s, s);
        asm volatile("cp.async.commit_group;" ::: "memory");
    }

    for (int kt = 0; kt < nk; kt++) {
        asm volatile("cp.async.wait_group %0;" :: "n"(STAGES - 2) : "memory");
        __syncthreads();
        {
            int pf = kt + STAGES - 1;
            if (pf < nk) load_stage(pf, pf & (STAGES - 1));
            asm volatile("cp.async.commit_group;" ::: "memory");
        }
        const int buf = kt & (STAGES - 1);

        #pragma unroll
        for (int k8 = 0; k8 < 16; k8 += 8) {
            uint32_t ah[4][4];
            #pragma unroll
            for (int mt = 0; mt < 4; mt++) {
                uint32_t addr = sA +
                    ((uint32_t)(((buf * 128 + aRow + mt * 16) * 20) + k8 + aColSel) << 2);
                LDMX4(ah[mt], addr);
            }
            uint32_t bh[4][2];
            #pragma unroll
            for (int nt = 0; nt < 4; nt++) {
                #pragma unroll
                for (int j = 0; j < 2; j++) {
                    float f = Bsm[(buf * 16 + k8 + bkRow + j * 4) * 136 + bnCol + nt * 8];
                    bh[nt][j] = __float_as_uint(CVTB ? cvt_tf32(f) : f);
                }
            }
            #pragma unroll
            for (int mt = 0; mt < 4; mt++)
                #pragma unroll
                for (int nt = 0; nt < 4; nt++)
                    MMA_TF32(acc[mt][nt], ah[mt], bh[nt]);
        }
    }

    // MODE 2: stage transposed x tile (shortcut) through smem (pitch 129)
    if (MODE == 2) {
        asm volatile("cp.async.wait_group 0;" ::: "memory");
        __syncthreads();
        #pragma unroll
        for (int it = 0; it < 16; it++) {
            int id = t + it * 256;
            int cc = id >> 5;
            int r4 = (id & 31) * 4;
            float4 xv = *reinterpret_cast<const float4*>(
                &E1[(long long)(n0 + cc) * M + m0 + r4]);
            smem[(r4 + 0) * 129 + cc] = xv.x;
            smem[(r4 + 1) * 129 + cc] = xv.y;
            smem[(r4 + 2) * 129 + cc] = xv.z;
            smem[(r4 + 3) * 129 + cc] = xv.w;
        }
        __syncthreads();
    }

    #pragma unroll
    for (int mt = 0; mt < 4; mt++) {
        #pragma unroll
        for (int half = 0; half < 2; half++) {
            int r = m0 + wm0 + mt * 16 + (lane >> 2) + half * 8;
            #pragma unroll
            for (int nt = 0; nt < 4; nt++) {
                int c = n0 + wn0 + nt * 8 + (lane & 3) * 2;
                float v0 = acc[mt][nt][half * 2 + 0];
                float v1 = acc[mt][nt][half * 2 + 1];
                long long off = (long long)r * N + c;
                if (MODE == 0) { float b = E0[r]; v0 += b; v1 += b; }
                if (MODE == 2) {
                    float zz = E0[r];
                    int li = (r - m0) * 129 + (c - n0);
                    v0 = v0 * zz + smem[li];
                    v1 = v1 * zz + smem[li + 1];
                }
                if (MODE == 3) { v0 += E0[c]; v1 += E0[c + 1]; }
                if (MODE == 4) {
                    float2 s = *reinterpret_cast<const float2*>(&E1[off]);
                    v0 += E0[c] + s.x; v1 += E0[c + 1] + s.y;
                }
                if (RND) { v0 = cvt_tf32(v0); v1 = cvt_tf32(v1); }
                *reinterpret_cast<float2*>(&C[off]) = make_float2(v0, v1);
            }
        }
    }
}

// ---------------- reduce 4 split-K partials + tf32 round --------------------
__global__ void reduce_kv(const float* __restrict__ p, float* __restrict__ out)
{
    const int per = CC * CC / 4;
    int i = blockIdx.x * 256 + threadIdx.x;
    if (i >= NB * per) return;
    int b = i / per, e = i % per;
    const float4* p4 = reinterpret_cast<const float4*>(p);
    float4 s0 = p4[((long long)b * 4 + 0) * per + e];
    float4 s1 = p4[((long long)b * 4 + 1) * per + e];
    float4 s2 = p4[((long long)b * 4 + 2) * per + e];
    float4 s3 = p4[((long long)b * 4 + 3) * per + e];
    float4 o;
    o.x = cvt_tf32(s0.x + s1.x + s2.x + s3.x);
    o.y = cvt_tf32(s0.y + s1.y + s2.y + s3.y);
    o.z = cvt_tf32(s0.z + s1.z + s2.z + s3.z);
    o.w = cvt_tf32(s0.w + s1.w + s2.w + s3.w);
    reinterpret_cast<float4*>(out)[i] = o;
}

// ---------------- elementwise tf32 round + bias concat -----------------------
__global__ void round_tf32_kernel(const float* __restrict__ in, float* __restrict__ out, int n4)
{
    int i = blockIdx.x * blockDim.x + threadIdx.x;
    if (i < n4) {
        float4 v = reinterpret_cast<const float4*>(in)[i];
        v.x = cvt_tf32(v.x); v.y = cvt_tf32(v.y);
        v.z = cvt_tf32(v.z); v.w = cvt_tf32(v.w);
        reinterpret_cast<float4*>(out)[i] = v;
    }
}

__global__ void concat_bias(const float* __restrict__ b0, const float* __restrict__ b1,
                            const float* __restrict__ b2, float* __restrict__ out)
{
    int i = blockIdx.x * blockDim.x + threadIdx.x;
    if (i < CC)            out[i] = b0[i];
    else if (i < 2 * CC)   out[i] = b1[i - CC];
    else if (i < 3 * CC)   out[i] = b2[i - 2 * CC];
}

// ---------------- column softmax: partial stats + combine -------------------
__global__ void colsm_partial(const float* __restrict__ q,
                              float* __restrict__ pm, float* __restrict__ ps)
{
    int b = blockIdx.y, chunk = blockIdx.z;
    int col = blockIdx.x * 32 + threadIdx.x;
    int ry  = threadIdx.y;
    const float* base = q + (long long)b * QKS + col;
    int r0 = chunk * 256 + ry * 32;
    float m = -1e30f, s = 0.f;
    for (int i = r0; i < r0 + 32; ++i) {
        float v  = base[(long long)i * CC];
        float mn = fmaxf(m, v);
        s = s * __expf(m - mn) + __expf(v - mn);
        m = mn;
    }
    __shared__ float sm[8][32], ssh[8][32];
    sm[ry][threadIdx.x] = m; ssh[ry][threadIdx.x] = s;
    __syncthreads();
    if (ry == 0) {
        float M = sm[0][threadIdx.x], S = ssh[0][threadIdx.x];
        #pragma unroll
        for (int r2 = 1; r2 < 8; r2++) {
            float m2 = sm[r2][threadIdx.x], s2 = ssh[r2][threadIdx.x];
            float mn = fmaxf(M, m2);
            S = S * __expf(M - mn) + s2 * __expf(m2 - mn);
            M = mn;
        }
        int idx = (b * CC + col) * KCHUNK + chunk;
        pm[idx] = M; ps[idx] = S;
    }
}

__global__ void colsm_combine(const float* __restrict__ pm, const float* __restrict__ ps,
                              const float* __restrict__ scale,
                              float* __restrict__ fm, float* __restrict__ fa,
                              float* __restrict__ fb)
{
    int i = blockIdx.x * blockDim.x + threadIdx.x;
    if (i >= NB * CC) return;
    float M = -1e30f, S = 0.f;
    #pragma unroll
    for (int c = 0; c < KCHUNK; c++) {
        float m2 = pm[i * KCHUNK + c], s2 = ps[i * KCHUNK + c];
        float mn = fmaxf(M, m2);
        S = S * __expf(M - mn) + s2 * __expf(m2 - mn);
        M = mn;
    }
    float isc = 1.f / log1pf(__expf(scale[i & (CC - 1)]));
    fm[i] = M;
    fa[i] = (1.f / S) * isc;
    fb[i] = 1e-6f * isc;
}

// ---------------- fused: col-softmax normalize + row renorm^3 + z -----------
__global__ void rownorm_pow3_z(float* __restrict__ qkv, const float* __restrict__ fm,
                               const float* __restrict__ fa, const float* __restrict__ fb,
                               const float* __restrict__ ksum, float* __restrict__ z)
{
    long long row = blockIdx.x;
    int b  = (int)(row >> 12);
    int ii = (int)(row & 4095);
    float* p = qkv + (long long)b * QKS + (long long)ii * CC;
    const float* ks = ksum + b * CC;
    int t = threadIdx.x;   // 128
    int c4 = t * 4;

    float4 raw = *reinterpret_cast<const float4*>(p + c4);
    float4 M4  = *reinterpret_cast<const float4*>(fm + b * CC + c4);
    float4 A4  = *reinterpret_cast<const float4*>(fa + b * CC + c4);
    float4 B4  = *reinterpret_cast<const float4*>(fb + b * CC + c4);

    float v[4];
    v[0] = __expf(raw.x - M4.x) * A4.x + B4.x;
    v[1] = __expf(raw.y - M4.y) * A4.y + B4.y;
    v[2] = __expf(raw.z - M4.z) * A4.z + B4.z;
    v[3] = __expf(raw.w - M4.w) * A4.w + B4.w;

    float s1 = 0.f;
    #pragma unroll
    for (int r = 0; r < 4; r++) s1 += v[r] * v[r];
    s1 = blockReduceSum(s1);
    float u3[4];
    float s3 = 0.f;
    #pragma unroll
    for (int r = 0; r < 4; r++) { u3[r] = v[r] * v[r] * v[r]; s3 += u3[r] * u3[r]; }
    s3 = blockReduceSum(s3);
    float f = sqrtf(s1) / sqrtf(s3);
    float o[4], dot = 0.f;
    #pragma unroll
    for (int r = 0; r < 4; r++) {
        o[r] = cvt_tf32(u3[r] * f);
        dot += o[r] * ks[c4 + r];
    }
    *reinterpret_cast<float4*>(p + c4) = make_float4(o[0], o[1], o[2], o[3]);
    dot = blockReduceSum(dot);
    if (t == 0) z[row] = 1.f / (dot + 1e-6f);
}

// ---------------- k: row softmax + renorm + ksum, writes kT directly --------
__global__ void __launch_bounds__(256)
softmax_row_k_t(const float* __restrict__ kbase, const float* __restrict__ scale,
                float* __restrict__ ksum, float* __restrict__ kt)
{
    extern __shared__ float sm[];   // [32][513]
    int blk = blockIdx.x;
    int b   = blk >> 7;
    int s0  = (blk & 127) * 32;
    const float* kb = kbase + (long long)b * QKS + (long long)s0 * CC;
    int warp = threadIdx.x >> 5, lane = threadIdx.x & 31;

    for (int rr = warp; rr < 32; rr += 8) {
        const float* p = kb + (long long)rr * CC;
        float v[16];
        #pragma unroll
        for (int j = 0; j < 4; j++)
            *reinterpret_cast<float4*>(&v[j * 4]) =
                *reinterpret_cast<const float4*>(&p[j * 128 + lane * 4]);
        float mx = v[0];
        #pragma unroll
        for (int e = 1; e < 16; e++) mx = fmaxf(mx, v[e]);
        #pragma unroll
        for (int o = 16; o > 0; o >>= 1) mx = fmaxf(mx, __shfl_xor_sync(0xffffffffu, mx, o));
        float se = 0.f;
        #pragma unroll
        for (int e = 0; e < 16; e++) se += __expf(v[e] - mx);
        #pragma unroll
        for (int o = 16; o > 0; o >>= 1) se += __shfl_xor_sync(0xffffffffu, se, o);
        float inv = 1.f / se;
        float u[16], s1 = 0.f, s3 = 0.f;
        #pragma unroll
        for (int j = 0; j < 4; j++)
            #pragma unroll
            for (int e = 0; e < 4; e++) {
                int c = j * 128 + lane * 4 + e;
                float isc = 1.f / log1pf(__expf(scale[c]));
                float uu = (__expf(v[j * 4 + e] - mx) * inv + 1e-6f) * isc;
                u[j * 4 + e] = uu;
                s1 += uu * uu;
                float u3 = uu * uu * uu;
                s3 += u3 * u3;
            }
        #pragma unroll
        for (int o = 16; o > 0; o >>= 1) s1 += __shfl_xor_sync(0xffffffffu, s1, o);
        #pragma unroll
        for (int o = 16; o > 0; o >>= 1) s3 += __shfl_xor_sync(0xffffffffu, s3, o);
        float f = sqrtf(s1) / sqrtf(s3);
        #pragma unroll
        for (int j = 0; j < 4; j++)
            #pragma unroll
            for (int e = 0; e < 4; e++) {
                int c = j * 128 + lane * 4 + e;
                float uu = u[j * 4 + e];
                float o3 = cvt_tf32(uu * uu * uu * f);
                sm[rr * 513 + c] = o3;
                atomicAdd(&ksum[b * CC + c], o3);
            }
    }
    __syncthreads();
    float* ko = kt + (long long)b * CC * SS + s0;
    for (int c = warp; c < CC; c += 8)
        ko[(long long)c * SS + lane] = sm[lane * 513 + c];
}

__global__ void zero_ksum(float* __restrict__ ksum)
{
    int i = blockIdx.x * blockDim.x + threadIdx.x;
    if (i < NB * CC) ksum[i] = 0.f;
}

// ---------------- LayerNorm over C=512 (tf32-rounded out) ------------------
__global__ void layernorm512(const float* __restrict__ in, float* __restrict__ out,
                             const float* __restrict__ g, const float* __restrict__ bta)
{
    long long row = blockIdx.x;
    const float* p = in + row * CC;
    int t = threadIdx.x;
    float4 f4 = *reinterpret_cast<const float4*>(p + t * 4);
    float v[4] = { f4.x, f4.y, f4.z, f4.w };
    float s = v[0] + v[1] + v[2] + v[3];
    s = blockReduceSum(s);
    float mean = s * (1.f / (float)CC);
    float s2 = 0.f;
    #pragma unroll
    for (int r = 0; r < 4; r++) { float d = v[r] - mean; s2 += d * d; }
    s2 = blockReduceSum(s2);
    float rstd = rsqrtf(s2 * (1.f / (float)CC) + 1e-5f);
    float o[4];
    #pragma unroll
    for (int r = 0; r < 4; r++) {
        int c = t * 4 + r;
        o[r] = cvt_tf32((v[r] - mean) * rstd * g[c] + bta[c]);
    }
    *reinterpret_cast<float4*>(out + row * CC + t * 4) = make_float4(o[0], o[1], o[2], o[3]);
}

// ---------------- 8-token dwconv 3x3 + residual + LN(HID) + GELU -----------
// Block: 8 consecutive x-tokens, 256 threads, 8 channels/thread.
__global__ void __launch_bounds__(256)
dw_ln_gelu8(const float* __restrict__ a, const float* __restrict__ w,
            const float* __restrict__ wb, const float* __restrict__ g,
            const float* __restrict__ beta, float* __restrict__ out)
{
    long long blk = blockIdx.x;          // NB*SS/8
    int b  = (int)(blk >> 9);            // 512 blocks per batch
    int s8 = (int)(blk & 511) * 8;
    int y  = s8 >> 6, x0 = s8 & 63;
    int t  = threadIdx.x;
    const float* ab = a + (long long)b * SS * HD;

    float acc[8][8];
    #pragma unroll
    for (int j = 0; j < 8; j++)
        #pragma unroll
        for (int r = 0; r < 8; r++) acc[j][r] = wb[r * 256 + t];

    // window: 3 rows x 10 cols (x0-1 .. x0+8)
    #pragma unroll
    for (int dy = 0; dy < 3; dy++) {
        int yy = y - 1 + dy;
        if (yy < 0 || yy > 63) continue;
        #pragma unroll
        for (int dx = 0; dx < 10; dx++) {
            int xx = x0 - 1 + dx;
            if (xx < 0 || xx > 63) continue;
            float win[8];
            const float* rowp = ab + (long long)(yy * 64 + xx) * HD;
            #pragma unroll
            for (int r = 0; r < 8; r++) win[r] = rowp[r * 256 + t];
            #pragma unroll
            for (int j = 0; j < 8; j++) {
                int kx = dx - j;          // = xx - (x0+j) + 1
                if (kx >= 0 && kx < 3) {
                    #pragma unroll
                    for (int r = 0; r < 8; r++)
                        acc[j][r] += w[(r * 256 + t) * 9 + dy * 3 + kx] * win[r];
                }
            }
        }
    }
    // + a (residual before LN)
    #pragma unroll
    for (int j = 0; j < 8; j++) {
        const float* selfp = ab + (long long)(s8 + j) * HD;
        #pragma unroll
        for (int r = 0; r < 8; r++) acc[j][r] += selfp[r * 256 + t];
    }

    // LN over HD per token (two quads reduced together)
    float4 sumA, sumB;
    sumA = make_float4(0.f, 0.f, 0.f, 0.f);
    sumB = make_float4(0.f, 0.f, 0.f, 0.f);
    #pragma unroll
    for (int r = 0; r < 8; r++) {
        sumA.x += acc[0][r]; sumA.y += acc[1][r];
        sumA.z += acc[2][r]; sumA.w += acc[3][r];
        sumB.x += acc[4][r]; sumB.y += acc[5][r];
        sumB.z += acc[6][r]; sumB.w += acc[7][r];
    }
    sumA = blockReduceSum4(sumA);
    sumB = blockReduceSum4(sumB);
    float mean[8] = { sumA.x * (1.f / HD), sumA.y * (1.f / HD),
                      sumA.z * (1.f / HD), sumA.w * (1.f / HD),
                      sumB.x * (1.f / HD), sumB.y * (1.f / HD),
                      sumB.z * (1.f / HD), sumB.w * (1.f / HD) };
    float4 sqA, sqB;
    sqA = make_float4(0.f, 0.f, 0.f, 0.f);
    sqB = make_float4(0.f, 0.f, 0.f, 0.f);
    #pragma unroll
    for (int r = 0; r < 8; r++) {
        float d0 = acc[0][r] - mean[0]; sqA.x += d0 * d0;
        float d1 = acc[1][r] - mean[1]; sqA.y += d1 * d1;
        float d2 = acc[2][r] - mean[2]; sqA.z += d2 * d2;
        float d3 = acc[3][r] - mean[3]; sqA.w += d3 * d3;
        float d4 = acc[4][r] - mean[4]; sqB.x += d4 * d4;
        float d5 = acc[5][r] - mean[5]; sqB.y += d5 * d5;
        float d6 = acc[6][r] - mean[6]; sqB.z += d6 * d6;
        float d7 = acc[7][r] - mean[7]; sqB.w += d7 * d7;
    }
    sqA = blockReduceSum4(sqA);
    sqB = blockReduceSum4(sqB);
    float rstd[8] = { rsqrtf(sqA.x * (1.f / HD) + 1e-5f), rsqrtf(sqA.y * (1.f / HD) + 1e-5f),
                      rsqrtf(sqA.z * (1.f / HD) + 1e-5f), rsqrtf(sqA.w * (1.f / HD) + 1e-5f),
                      rsqrtf(sqB.x * (1.f / HD) + 1e-5f), rsqrtf(sqB.y * (1.f / HD) + 1e-5f),
                      rsqrtf(sqB.z * (1.f / HD) + 1e-5f), rsqrtf(sqB.w * (1.f / HD) + 1e-5f) };

    #pragma unroll
    for (int j = 0; j < 8; j++) {
        float* op = out + ((long long)b * SS + s8 + j) * HD;
        #pragma unroll
        for (int r = 0; r < 8; r++) {
            int h = r * 256 + t;
            float yv = (acc[j][r] - mean[j]) * rstd[j] * g[h] + beta[h];
            float ge = 0.5f * yv * (1.f + erff(yv * 0.70710678118654752f));
            op[h] = cvt_tf32(ge);
        }
    }
}

// ---------------- launch ----------------------------------------------------
extern "C" void kernel_launch(void* const* d_in, const int* in_sizes, int n_in,
                              void* d_out, int out_size)
{
    const float* x      = (const float*)d_in[0];
    const float* Wq     = (const float*)d_in[1];
    const float* bq     = (const float*)d_in[2];
    const float* Wk     = (const float*)d_in[3];
    const float* bk     = (const float*)d_in[4];
    const float* Wv     = (const float*)d_in[5];
    const float* bv     = (const float*)d_in[6];
    const float* scale  = (const float*)d_in[7];
    const float* fc1_w  = (const float*)d_in[8];
    const float* fc1_b  = (const float*)d_in[9];
    const float* dw_w   = (const float*)d_in[10];
    const float* dw_b   = (const float*)d_in[11];
    const float* fc2_w  = (const float*)d_in[12];
    const float* fc2_b  = (const float*)d_in[13];
    const float* ln1_g  = (const float*)d_in[14];
    const float* ln1_b  = (const float*)d_in[15];
    const float* lnm_g  = (const float*)d_in[16];
    const float* lnm_b  = (const float*)d_in[17];
    float* out = (float*)d_out;

    void *pqkv, *pxr, *pkt, *penh, *pt, *pa, *pax, *pkv, *pkvp;
    void *pwqkv, *pbqkv, *pw1, *pw2, *pksum, *pz;
    void *pcpm, *pcps, *pcfm, *pcfa, *pcfb;
    cudaGetSymbolAddress(&pqkv, g_qkv);
    cudaGetSymbolAddress(&pxr,  g_xr);
    cudaGetSymbolAddress(&pkt,  g_kt);
    cudaGetSymbolAddress(&penh, g_enh);
    cudaGetSymbolAddress(&pt,   g_t);
    cudaGetSymbolAddress(&pa,   g_a);
    cudaGetSymbolAddress(&pax,  g_ax);
    cudaGetSymbolAddress(&pkv,  g_kv);
    cudaGetSymbolAddress(&pkvp, g_kvp);
    cudaGetSymbolAddress(&pwqkv,g_wqkv);
    cudaGetSymbolAddress(&pbqkv,g_bqkv);
    cudaGetSymbolAddress(&pw1,  g_w1);
    cudaGetSymbolAddress(&pw2,  g_w2);
    cudaGetSymbolAddress(&pksum,g_ksum);
    cudaGetSymbolAddress(&pz,   g_z);
    cudaGetSymbolAddress(&pcpm, g_cpm);
    cudaGetSymbolAddress(&pcps, g_cps);
    cudaGetSymbolAddress(&pcfm, g_cfm);
    cudaGetSymbolAddress(&pcfa, g_cfa);
    cudaGetSymbolAddress(&pcfb, g_cfb);

    cudaFuncSetAttribute(gemm_tc<0,false,true ,false>, cudaFuncAttributeMaxDynamicSharedMemorySize, SMEM_GEMM_BYTES);
    cudaFuncSetAttribute(gemm_tc<1,false,false,true >, cudaFuncAttributeMaxDynamicSharedMemorySize, SMEM_GEMM_BYTES);
    cudaFuncSetAttribute(gemm_tc<2,false,false,false>, cudaFuncAttributeMaxDynamicSharedMemorySize, SMEM_GEMM_BYTES);
    cudaFuncSetAttribute(gemm_tc<3,false,false,false>, cudaFuncAttributeMaxDynamicSharedMemorySize, SMEM_GEMM_BYTES);
    cudaFuncSetAttribute(gemm_tc<4,false,false,false>, cudaFuncAttributeMaxDynamicSharedMemorySize, SMEM_GEMM_BYTES);
    cudaFuncSetAttribute(softmax_row_k_t, cudaFuncAttributeMaxDynamicSharedMemorySize, SMEM_SRKT);

    const long long BS  = (long long)CC * SS;
    const long long KVS = (long long)CC * CC;
    float* fqkv = (float*)pqkv;
    float* fw   = (float*)pwqkv;

    // 0. weight + input prep (all pre-rounded -> no cvt in any GEMM mainloop)
    round_tf32_kernel<<<(CC*HD/4 + 255)/256, 256>>>(fc1_w, (float*)pw1, CC*HD/4);
    round_tf32_kernel<<<(HD*CC/4 + 255)/256, 256>>>(fc2_w, (float*)pw2, HD*CC/4);
    round_tf32_kernel<<<(CC*CC/4 + 255)/256, 256>>>(Wq, fw,             CC*CC/4);
    round_tf32_kernel<<<(CC*CC/4 + 255)/256, 256>>>(Wk, fw + CC*CC,     CC*CC/4);
    round_tf32_kernel<<<(CC*CC/4 + 255)/256, 256>>>(Wv, fw + 2*CC*CC,   CC*CC/4);
    round_tf32_kernel<<<(int)((NB*BS/4 + 255)/256), 256>>>(x, (float*)pxr, (int)(NB*BS/4));
    concat_bias<<<6, 256>>>(bq, bk, bv, (float*)pbqkv);

    // 1. merged qkv GEMM (rounded out: v is consumed raw by kv GEMM)
    gemm_tc<0,false,true ,false><<<dim3(SS/128, 1536/128, NB), 256, SMEM_GEMM_BYTES>>>(
        fw, (float*)pxr, fqkv, 1536, SS, CC, 0, BS, QKS, (float*)pbqkv, nullptr, 0, 0);

    // 2. k path: softmax + renorm + ksum, writing kT directly
    zero_ksum<<<4, 1024>>>((float*)pksum);
    softmax_row_k_t<<<NB*SS/32, 256, SMEM_SRKT>>>(fqkv + BS, scale, (float*)pksum, (float*)pkt);

    // 3. q path: col-softmax stats, combine, fused normalize+renorm^3+z
    colsm_partial<<<dim3(CC/32, NB, KCHUNK), dim3(32, 8)>>>(fqkv, (float*)pcpm, (float*)pcps);
    colsm_combine<<<(NB*CC + 255)/256, 256>>>((float*)pcpm, (float*)pcps, scale,
                                              (float*)pcfm, (float*)pcfa, (float*)pcfb);
    rownorm_pow3_z<<<NB*SS, 128>>>(fqkv, (float*)pcfm, (float*)pcfa, (float*)pcfb,
                                   (float*)pksum, (float*)pz);

    // 4. kv = kT @ v with 4-way split-K, then reduce + round
    gemm_tc<1,false,false,true ><<<dim3(CC/128, CC/128, NB*4), 256, SMEM_GEMM_BYTES>>>(
        (float*)pkt, fqkv + 2*BS, (float*)pkvp, CC, CC, SS, BS, QKS, KVS,
        nullptr, nullptr, 0, 0);
    reduce_kv<<<(NB*CC*CC/4 + 255)/256, 256>>>((float*)pkvp, (float*)pkv);

    // 5. enhanced = x^T + z * (q @ kv)
    gemm_tc<2,false,false,false><<<dim3(CC/128, SS/128, NB), 256, SMEM_GEMM_BYTES>>>(
        fqkv, (float*)pkv, (float*)penh, SS, CC, CC, QKS, KVS, BS,
        (float*)pz, x, SS, BS);

    // 6. t = LN(enhanced)
    layernorm512<<<NB*SS, 128>>>((float*)penh, (float*)pt, lnm_g, lnm_b);

    // 7. a = t @ w1 + fc1_b
    gemm_tc<3,false,false,false><<<dim3(HD/128, (NB*SS)/128, 1), 256, SMEM_GEMM_BYTES>>>(
        (float*)pt, (float*)pw1, (float*)pa, NB*SS, HD, CC, 0, 0, 0,
        fc1_b, nullptr, 0, 0);

    // 8. ax = gelu(LN(dwconv3x3(a) + dw_b + a))  [8-token tiles]
    dw_ln_gelu8<<<NB*SS/8, 256>>>((float*)pa, dw_w, dw_b, ln1_g, ln1_b, (float*)pax);

    // 9. out = enhanced + ax @ w2 + fc2_b
    gemm_tc<4,false,false,false><<<dim3(CC/128, (NB*SS)/128, 1), 256, SMEM_GEMM_BYTES>>>(
        (float*)pax, (float*)pw2, out, NB*SS, CC, HD, 0, 0, 0,
        fc2_b, (float*)penh, 0, 0);
}

// round 16
// speedup vs baseline: 1.0103x; 1.0103x over previous
#include <cuda_runtime.h>
#include <cuda_bf16.h>
#include <math.h>
#include <stdint.h>

// Problem dims
#define NB 8
#define CC 512
#define SS 4096     // N = H*W tokens
#define HD 2048     // HID = 4*C
#define HH 64

#define STAGES 4
#define KCHUNK 16   // column-softmax chunks

#define QKS (3LL*CC*SS)   // per-batch stride of the merged qkv buffer

// ---------------- scratch (device globals; no allocation allowed) ----------
__device__ float g_qkv[(long long)NB*3*CC*SS];   // 192MB: per batch [q|k|v]
__device__ float g_xr [(long long)NB*CC*SS];     // tf32-rounded x
__device__ float g_kt [(long long)NB*CC*SS];
__device__ float g_enh[(long long)NB*SS*CC];
__device__ float g_t  [(long long)NB*SS*CC];
__device__ float g_a  [(long long)NB*SS*HD];
__device__ float g_ax [(long long)NB*SS*HD];
__device__ float g_kv [(long long)NB*CC*CC];
__device__ float g_kvp[(long long)2*NB*CC*CC];   // split-K partials (2-way)
__device__ float g_wqkv[3*CC*CC];                // stacked, tf32-rounded
__device__ float g_bqkv[3*CC];
__device__ float g_w1 [(long long)CC*HD];
__device__ float g_w2 [(long long)HD*CC];
__device__ float g_ksum[NB*CC];
__device__ float g_z  [NB*SS];
__device__ float g_cpm[NB*CC*KCHUNK];
__device__ float g_cps[NB*CC*KCHUNK];
__device__ float g_cfm[NB*CC];                   // per-col max
__device__ float g_cfa[NB*CC];                   // per-col inv*isc
__device__ float g_cfb[NB*CC];                   // per-col 1e-6*isc

// ---------------- helpers ---------------------------------------------------
__device__ __forceinline__ float blockReduceSum(float val) {
    __shared__ float sh[32];
    int lane = threadIdx.x & 31, wid = threadIdx.x >> 5;
    #pragma unroll
    for (int o = 16; o > 0; o >>= 1) val += __shfl_xor_sync(0xffffffff, val, o);
    if (lane == 0) sh[wid] = val;
    __syncthreads();
    float tot = 0.f;
    if (wid == 0) {
        tot = (lane < (int)(blockDim.x >> 5)) ? sh[lane] : 0.f;
        #pragma unroll
        for (int o = 16; o > 0; o >>= 1) tot += __shfl_xor_sync(0xffffffff, tot, o);
        if (lane == 0) sh[0] = tot;
    }
    __syncthreads();
    tot = sh[0];
    __syncthreads();
    return tot;
}

__device__ __forceinline__ float4 blockReduceSum4(float4 v) {
    __shared__ float4 sh[32];
    int lane = threadIdx.x & 31, wid = threadIdx.x >> 5;
    #pragma unroll
    for (int o = 16; o > 0; o >>= 1) {
        v.x += __shfl_xor_sync(0xffffffff, v.x, o);
        v.y += __shfl_xor_sync(0xffffffff, v.y, o);
        v.z += __shfl_xor_sync(0xffffffff, v.z, o);
        v.w += __shfl_xor_sync(0xffffffff, v.w, o);
    }
    if (lane == 0) sh[wid] = v;
    __syncthreads();
    float4 tot = make_float4(0.f, 0.f, 0.f, 0.f);
    if (wid == 0) {
        if (lane < (int)(blockDim.x >> 5)) tot = sh[lane];
        #pragma unroll
        for (int o = 16; o > 0; o >>= 1) {
            tot.x += __shfl_xor_sync(0xffffffff, tot.x, o);
            tot.y += __shfl_xor_sync(0xffffffff, tot.y, o);
            tot.z += __shfl_xor_sync(0xffffffff, tot.z, o);
            tot.w += __shfl_xor_sync(0xffffffff, tot.w, o);
        }
        if (lane == 0) sh[0] = tot;
    }
    __syncthreads();
    tot = sh[0];
    __syncthreads();
    return tot;
}

__device__ __forceinline__ float cvt_tf32(float v) {
    uint32_t u;
    asm("cvt.rna.tf32.f32 %0, %1;" : "=r"(u) : "f"(v));
    return __uint_as_float(u);
}

__device__ __forceinline__ void cp16(uint32_t s, const void* g) {
    asm volatile("cp.async.cg.shared.global [%0], [%1], 16;" :: "r"(s), "l"(g));
}

#define MMA_TF32(d, a, b) \
    asm volatile("mma.sync.aligned.m16n8k8.row.col.f32.tf32.tf32.f32 " \
        "{%0,%1,%2,%3},{%4,%5,%6,%7},{%8,%9},{%0,%1,%2,%3};" \
        : "+f"(d[0]), "+f"(d[1]), "+f"(d[2]), "+f"(d[3]) \
        : "r"(a[0]), "r"(a[1]), "r"(a[2]), "r"(a[3]), "r"(b[0]), "r"(b[1]))

#define LDMX4(dst, addr) \
    asm volatile("ldmatrix.sync.aligned.m8n8.x4.shared.b16 {%0,%1,%2,%3}, [%4];" \
        : "=r"(dst[0]), "=r"(dst[1]), "=r"(dst[2]), "=r"(dst[3]) : "r"(addr) : "memory")

#define AS_FLOATS (STAGES * 128 * 20)
#define BS_FLOATS (STAGES * 16 * 136)
#define SMEM_GEMM_BYTES ((AS_FLOATS + BS_FLOATS) * 4)
#define SMEM_SRKT (32 * 513 * 4)

// ---------------- single-pass TF32 GEMM, BK=16, 4-stage cp.async -----------
// All inputs pre-rounded to tf32.
// MODE: 0 = +bias[row]; 1 = plain; 2 = acc*z[row] + x^T tile (e1 = x, NCHW);
//       3 = +bias[col]; 4 = +bias[col]+res.  RND: tf32-round stores.
//       SPLITK: 2-way K split (blockIdx.z = batch*2+slice, keff = 2048).
template<int MODE, bool CVTB, bool RND, bool SPLITK>
__global__ void __launch_bounds__(256, 2)
gemm_tc(const float* __restrict__ A, const float* __restrict__ B,
        float* __restrict__ C, int M, int N, int K,
        long long strA, long long strB, long long strC,
        const float* __restrict__ e0, const float* __restrict__ e1,
        long long strE0, long long strE1)
{
    extern __shared__ float smem[];
    float* Asm = smem;
    float* Bsm = smem + AS_FLOATS;

    int bz = blockIdx.z;
    int keff = K;
    if (SPLITK) {
        int slice = bz & 1;
        int batch = bz >> 1;
        A += (long long)batch * strA + slice * 2048;
        B += (long long)batch * strB + (long long)slice * 2048 * N;
        C += (long long)bz * strC;
        keff = 2048;
    } else {
        A += (long long)bz * strA;
        B += (long long)bz * strB;
        C += (long long)bz * strC;
    }
    const float* E0 = e0 ? e0 + (long long)bz * strE0 : nullptr;
    const float* E1 = e1 ? e1 + (long long)bz * strE1 : nullptr;

    const int t    = threadIdx.x;
    const int lane = t & 31, warp = t >> 5;
    const int m0   = blockIdx.y * 128, n0 = blockIdx.x * 128;
    const int wm0  = (warp & 1) * 64;
    const int wn0  = (warp >> 1) * 32;

    const int arow = t >> 1,  acol = (t & 1) * 8;
    const int brow = t >> 4,  bcol = (t & 15) * 8;

    const uint32_t sA = (uint32_t)__cvta_generic_to_shared(Asm);
    const uint32_t sB = (uint32_t)__cvta_generic_to_shared(Bsm);

    float acc[4][4][4];
    #pragma unroll
    for (int i = 0; i < 4; i++)
        #pragma unroll
        for (int j = 0; j < 4; j++)
            #pragma unroll
            for (int r = 0; r < 4; r++) acc[i][j][r] = 0.f;

    const int aRow    = wm0 + (lane & 15);
    const int aColSel = (lane >> 4) << 2;
    const int bkRow   = lane & 3;
    const int bnCol   = wn0 + (lane >> 2);

    const int nk = keff >> 4;

    auto load_stage = [&](int kt, int buf) {
        const float* ap = A + (long long)(m0 + arow) * K + (kt << 4) + acol;
        uint32_t sa = sA + (uint32_t)(((buf * 128 + arow) * 20 + acol) << 2);
        cp16(sa, ap);
        cp16(sa + 16, ap + 4);
        const float* bp = B + (long long)((kt << 4) + brow) * N + n0 + bcol;
        uint32_t sb = sB + (uint32_t)(((buf * 16 + brow) * 136 + bcol) << 2);
        cp16(sb, bp);
        cp16(sb + 16, bp + 4);
    };

    #pragma unroll
    for (int s = 0; s < STAGES - 1; s++) {
        if (s < nk) load_stage(s, s);
        asm volatile("cp.async.commit_group;" ::: "memory");
    }

    for (int kt = 0; kt < nk; kt++) {
        asm volatile("cp.async.wait_group %0;" :: "n"(STAGES - 2) : "memory");
        __syncthreads();
        {
            int pf = kt + STAGES - 1;
            if (pf < nk) load_stage(pf, pf & (STAGES - 1));
            asm volatile("cp.async.commit_group;" ::: "memory");
        }
        const int buf = kt & (STAGES - 1);

        #pragma unroll
        for (int k8 = 0; k8 < 16; k8 += 8) {
            uint32_t ah[4][4];
            #pragma unroll
            for (int mt = 0; mt < 4; mt++) {
                uint32_t addr = sA +
                    ((uint32_t)(((buf * 128 + aRow + mt * 16) * 20) + k8 + aColSel) << 2);
                LDMX4(ah[mt], addr);
            }
            uint32_t bh[4][2];
            #pragma unroll
            for (int nt = 0; nt < 4; nt++) {
                #pragma unroll
                for (int j = 0; j < 2; j++) {
                    float f = Bsm[(buf * 16 + k8 + bkRow + j * 4) * 136 + bnCol + nt * 8];
                    bh[nt][j] = __float_as_uint(CVTB ? cvt_tf32(f) : f);
                }
            }
            #pragma unroll
            for (int mt = 0; mt < 4; mt++)
                #pragma unroll
                for (int nt = 0; nt < 4; nt++)
                    MMA_TF32(acc[mt][nt], ah[mt], bh[nt]);
        }
    }

    // MODE 2: stage transposed x tile (shortcut) through smem (pitch 129)
    if (MODE == 2) {
        asm volatile("cp.async.wait_group 0;" ::: "memory");
        __syncthreads();
        #pragma unroll
        for (int it = 0; it < 16; it++) {
            int id = t + it * 256;
            int cc = id >> 5;
            int r4 = (id & 31) * 4;
            float4 xv = *reinterpret_cast<const float4*>(
                &E1[(long long)(n0 + cc) * M + m0 + r4]);
            smem[(r4 + 0) * 129 + cc] = xv.x;
            smem[(r4 + 1) * 129 + cc] = xv.y;
            smem[(r4 + 2) * 129 + cc] = xv.z;
            smem[(r4 + 3) * 129 + cc] = xv.w;
        }
        __syncthreads();
    }

    #pragma unroll
    for (int mt = 0; mt < 4; mt++) {
        #pragma unroll
        for (int half = 0; half < 2; half++) {
            int r = m0 + wm0 + mt * 16 + (lane >> 2) + half * 8;
            #pragma unroll
            for (int nt = 0; nt < 4; nt++) {
                int c = n0 + wn0 + nt * 8 + (lane & 3) * 2;
                float v0 = acc[mt][nt][half * 2 + 0];
                float v1 = acc[mt][nt][half * 2 + 1];
                long long off = (long long)r * N + c;
                if (MODE == 0) { float b = E0[r]; v0 += b; v1 += b; }
                if (MODE == 2) {
                    float zz = E0[r];
                    int li = (r - m0) * 129 + (c - n0);
                    v0 = v0 * zz + smem[li];
                    v1 = v1 * zz + smem[li + 1];
                }
                if (MODE == 3) { v0 += E0[c]; v1 += E0[c + 1]; }
                if (MODE == 4) {
                    float2 s = *reinterpret_cast<const float2*>(&E1[off]);
                    v0 += E0[c] + s.x; v1 += E0[c + 1] + s.y;
                }
                if (RND) { v0 = cvt_tf32(v0); v1 = cvt_tf32(v1); }
                *reinterpret_cast<float2*>(&C[off]) = make_float2(v0, v1);
            }
        }
    }
}

// ---------------- reduce 2 split-K partials + tf32 round --------------------
__global__ void reduce_kv(const float* __restrict__ p, float* __restrict__ out)
{
    const int per = CC * CC / 4;
    int i = blockIdx.x * 256 + threadIdx.x;
    if (i >= NB * per) return;
    int b = i / per, e = i % per;
    const float4* p4 = reinterpret_cast<const float4*>(p);
    float4 s0 = p4[((long long)b * 2 + 0) * per + e];
    float4 s1 = p4[((long long)b * 2 + 1) * per + e];
    float4 o;
    o.x = cvt_tf32(s0.x + s1.x);
    o.y = cvt_tf32(s0.y + s1.y);
    o.z = cvt_tf32(s0.z + s1.z);
    o.w = cvt_tf32(s0.w + s1.w);
    reinterpret_cast<float4*>(out)[i] = o;
}

// ---------------- elementwise tf32 round + bias concat -----------------------
__global__ void round_tf32_kernel(const float* __restrict__ in, float* __restrict__ out, int n4)
{
    int i = blockIdx.x * blockDim.x + threadIdx.x;
    if (i < n4) {
        float4 v = reinterpret_cast<const float4*>(in)[i];
        v.x = cvt_tf32(v.x); v.y = cvt_tf32(v.y);
        v.z = cvt_tf32(v.z); v.w = cvt_tf32(v.w);
        reinterpret_cast<float4*>(out)[i] = v;
    }
}

__global__ void concat_bias(const float* __restrict__ b0, const float* __restrict__ b1,
                            const float* __restrict__ b2, float* __restrict__ out)
{
    int i = blockIdx.x * blockDim.x + threadIdx.x;
    if (i < CC)            out[i] = b0[i];
    else if (i < 2 * CC)   out[i] = b1[i - CC];
    else if (i < 3 * CC)   out[i] = b2[i - 2 * CC];
}

// ---------------- column softmax: partial stats (two-pass, reg-resident) ----
__global__ void colsm_partial(const float* __restrict__ q,
                              float* __restrict__ pm, float* __restrict__ ps)
{
    int b = blockIdx.y, chunk = blockIdx.z;
    int col = blockIdx.x * 32 + threadIdx.x;
    int ry  = threadIdx.y;
    const float* base = q + (long long)b * QKS + col;
    int r0 = chunk * 256 + ry * 32;

    float v[32];
    #pragma unroll
    for (int i = 0; i < 32; i++)
        v[i] = base[(long long)(r0 + i) * CC];
    float m = v[0];
    #pragma unroll
    for (int i = 1; i < 32; i++) m = fmaxf(m, v[i]);
    float s = 0.f;
    #pragma unroll
    for (int i = 0; i < 32; i++) s += __expf(v[i] - m);

    __shared__ float sm[8][32], ssh[8][32];
    sm[ry][threadIdx.x] = m; ssh[ry][threadIdx.x] = s;
    __syncthreads();
    if (ry == 0) {
        float M = sm[0][threadIdx.x], S = ssh[0][threadIdx.x];
        #pragma unroll
        for (int r2 = 1; r2 < 8; r2++) {
            float m2 = sm[r2][threadIdx.x], s2 = ssh[r2][threadIdx.x];
            float mn = fmaxf(M, m2);
            S = S * __expf(M - mn) + s2 * __expf(m2 - mn);
            M = mn;
        }
        int idx = (b * CC + col) * KCHUNK + chunk;
        pm[idx] = M; ps[idx] = S;
    }
}

__global__ void colsm_combine(const float* __restrict__ pm, const float* __restrict__ ps,
                              const float* __restrict__ scale,
                              float* __restrict__ fm, float* __restrict__ fa,
                              float* __restrict__ fb)
{
    int i = blockIdx.x * blockDim.x + threadIdx.x;
    if (i >= NB * CC) return;
    float M = -1e30f, S = 0.f;
    #pragma unroll
    for (int c = 0; c < KCHUNK; c++) {
        float m2 = pm[i * KCHUNK + c], s2 = ps[i * KCHUNK + c];
        float mn = fmaxf(M, m2);
        S = S * __expf(M - mn) + s2 * __expf(m2 - mn);
        M = mn;
    }
    float isc = 1.f / log1pf(__expf(scale[i & (CC - 1)]));
    fm[i] = M;
    fa[i] = (1.f / S) * isc;
    fb[i] = 1e-6f * isc;
}

// ---------------- fused: col-softmax normalize + row renorm^3 + z -----------
__global__ void rownorm_pow3_z(float* __restrict__ qkv, const float* __restrict__ fm,
                               const float* __restrict__ fa, const float* __restrict__ fb,
                               const float* __restrict__ ksum, float* __restrict__ z)
{
    long long row = blockIdx.x;
    int b  = (int)(row >> 12);
    int ii = (int)(row & 4095);
    float* p = qkv + (long long)b * QKS + (long long)ii * CC;
    const float* ks = ksum + b * CC;
    int t = threadIdx.x;   // 128
    int c4 = t * 4;

    float4 raw = *reinterpret_cast<const float4*>(p + c4);
    float4 M4  = *reinterpret_cast<const float4*>(fm + b * CC + c4);
    float4 A4  = *reinterpret_cast<const float4*>(fa + b * CC + c4);
    float4 B4  = *reinterpret_cast<const float4*>(fb + b * CC + c4);

    float v[4];
    v[0] = __expf(raw.x - M4.x) * A4.x + B4.x;
    v[1] = __expf(raw.y - M4.y) * A4.y + B4.y;
    v[2] = __expf(raw.z - M4.z) * A4.z + B4.z;
    v[3] = __expf(raw.w - M4.w) * A4.w + B4.w;

    float s1 = 0.f;
    #pragma unroll
    for (int r = 0; r < 4; r++) s1 += v[r] * v[r];
    s1 = blockReduceSum(s1);
    float u3[4];
    float s3 = 0.f;
    #pragma unroll
    for (int r = 0; r < 4; r++) { u3[r] = v[r] * v[r] * v[r]; s3 += u3[r] * u3[r]; }
    s3 = blockReduceSum(s3);
    float f = sqrtf(s1) / sqrtf(s3);
    float o[4], dot = 0.f;
    #pragma unroll
    for (int r = 0; r < 4; r++) {
        o[r] = cvt_tf32(u3[r] * f);
        dot += o[r] * ks[c4 + r];
    }
    *reinterpret_cast<float4*>(p + c4) = make_float4(o[0], o[1], o[2], o[3]);
    dot = blockReduceSum(dot);
    if (t == 0) z[row] = 1.f / (dot + 1e-6f);
}

// ---------------- k: row softmax + renorm + ksum, writes kT directly --------
__global__ void __launch_bounds__(256)
softmax_row_k_t(const float* __restrict__ kbase, const float* __restrict__ scale,
                float* __restrict__ ksum, float* __restrict__ kt)
{
    extern __shared__ float sm[];   // [32][513]
    int blk = blockIdx.x;
    int b   = blk >> 7;
    int s0  = (blk & 127) * 32;
    const float* kb = kbase + (long long)b * QKS + (long long)s0 * CC;
    int warp = threadIdx.x >> 5, lane = threadIdx.x & 31;

    for (int rr = warp; rr < 32; rr += 8) {
        const float* p = kb + (long long)rr * CC;
        float v[16];
        #pragma unroll
        for (int j = 0; j < 4; j++)
            *reinterpret_cast<float4*>(&v[j * 4]) =
                *reinterpret_cast<const float4*>(&p[j * 128 + lane * 4]);
        float mx = v[0];
        #pragma unroll
        for (int e = 1; e < 16; e++) mx = fmaxf(mx, v[e]);
        #pragma unroll
        for (int o = 16; o > 0; o >>= 1) mx = fmaxf(mx, __shfl_xor_sync(0xffffffffu, mx, o));
        float se = 0.f;
        #pragma unroll
        for (int e = 0; e < 16; e++) se += __expf(v[e] - mx);
        #pragma unroll
        for (int o = 16; o > 0; o >>= 1) se += __shfl_xor_sync(0xffffffffu, se, o);
        float inv = 1.f / se;
        float u[16], s1 = 0.f, s3 = 0.f;
        #pragma unroll
        for (int j = 0; j < 4; j++)
            #pragma unroll
            for (int e = 0; e < 4; e++) {
                int c = j * 128 + lane * 4 + e;
                float isc = 1.f / log1pf(__expf(scale[c]));
                float uu = (__expf(v[j * 4 + e] - mx) * inv + 1e-6f) * isc;
                u[j * 4 + e] = uu;
                s1 += uu * uu;
                float u3 = uu * uu * uu;
                s3 += u3 * u3;
            }
        #pragma unroll
        for (int o = 16; o > 0; o >>= 1) s1 += __shfl_xor_sync(0xffffffffu, s1, o);
        #pragma unroll
        for (int o = 16; o > 0; o >>= 1) s3 += __shfl_xor_sync(0xffffffffu, s3, o);
        float f = sqrtf(s1) / sqrtf(s3);
        #pragma unroll
        for (int j = 0; j < 4; j++)
            #pragma unroll
            for (int e = 0; e < 4; e++) {
                int c = j * 128 + lane * 4 + e;
                float uu = u[j * 4 + e];
                float o3 = cvt_tf32(uu * uu * uu * f);
                sm[rr * 513 + c] = o3;
                atomicAdd(&ksum[b * CC + c], o3);
            }
    }
    __syncthreads();
    float* ko = kt + (long long)b * CC * SS + s0;
    for (int c = warp; c < CC; c += 8)
        ko[(long long)c * SS + lane] = sm[lane * 513 + c];
}

__global__ void zero_ksum(float* __restrict__ ksum)
{
    int i = blockIdx.x * blockDim.x + threadIdx.x;
    if (i < NB * CC) ksum[i] = 0.f;
}

// ---------------- LayerNorm over C=512 (tf32-rounded out) ------------------
__global__ void layernorm512(const float* __restrict__ in, float* __restrict__ out,
                             const float* __restrict__ g, const float* __restrict__ bta)
{
    long long row = blockIdx.x;
    const float* p = in + row * CC;
    int t = threadIdx.x;
    float4 f4 = *reinterpret_cast<const float4*>(p + t * 4);
    float v[4] = { f4.x, f4.y, f4.z, f4.w };
    float s = v[0] + v[1] + v[2] + v[3];
    s = blockReduceSum(s);
    float mean = s * (1.f / (float)CC);
    float s2 = 0.f;
    #pragma unroll
    for (int r = 0; r < 4; r++) { float d = v[r] - mean; s2 += d * d; }
    s2 = blockReduceSum(s2);
    float rstd = rsqrtf(s2 * (1.f / (float)CC) + 1e-5f);
    float o[4];
    #pragma unroll
    for (int r = 0; r < 4; r++) {
        int c = t * 4 + r;
        o[r] = cvt_tf32((v[r] - mean) * rstd * g[c] + bta[c]);
    }
    *reinterpret_cast<float4*>(out + row * CC + t * 4) = make_float4(o[0], o[1], o[2], o[3]);
}

// ---------------- 4-token dwconv 3x3 + residual + LN(HID) + GELU -----------
// Block: 4 consecutive x-tokens, 256 threads, 8 channels/thread.
__global__ void __launch_bounds__(256)
dw_ln_gelu4(const float* __restrict__ a, const float* __restrict__ w,
            const float* __restrict__ wb, const float* __restrict__ g,
            const float* __restrict__ beta, float* __restrict__ out)
{
    long long blk = blockIdx.x;          // NB*SS/4
    int b  = (int)(blk >> 10);           // 1024 blocks per batch
    int s4 = (int)(blk & 1023) * 4;
    int y  = s4 >> 6, x0 = s4 & 63;
    int t  = threadIdx.x;
    const float* ab = a + (long long)b * SS * HD;

    float acc[4][8];
    #pragma unroll
    for (int j = 0; j < 4; j++)
        #pragma unroll
        for (int r = 0; r < 8; r++) acc[j][r] = wb[r * 256 + t];

    // window: 3 rows x 6 cols (x0-1 .. x0+4)
    #pragma unroll
    for (int dy = 0; dy < 3; dy++) {
        int yy = y - 1 + dy;
        if (yy < 0 || yy > 63) continue;
        #pragma unroll
        for (int dx = 0; dx < 6; dx++) {
            int xx = x0 - 1 + dx;
            if (xx < 0 || xx > 63) continue;
            float win[8];
            const float* rowp = ab + (long long)(yy * 64 + xx) * HD;
            #pragma unroll
            for (int r = 0; r < 8; r++) win[r] = rowp[r * 256 + t];
            #pragma unroll
            for (int j = 0; j < 4; j++) {
                int kx = dx - j;          // = xx - (x0+j) + 1
                if (kx >= 0 && kx < 3) {
                    #pragma unroll
                    for (int r = 0; r < 8; r++)
                        acc[j][r] += w[(r * 256 + t) * 9 + dy * 3 + kx] * win[r];
                }
            }
        }
    }
    // + a (residual before LN)
    #pragma unroll
    for (int j = 0; j < 4; j++) {
        const float* selfp = ab + (long long)(s4 + j) * HD;
        #pragma unroll
        for (int r = 0; r < 8; r++) acc[j][r] += selfp[r * 256 + t];
    }

    // LN over HD per token (4 tokens reduced together)
    float4 sum;
    sum.x = 0.f; sum.y = 0.f; sum.z = 0.f; sum.w = 0.f;
    #pragma unroll
    for (int r = 0; r < 8; r++) {
        sum.x += acc[0][r]; sum.y += acc[1][r];
        sum.z += acc[2][r]; sum.w += acc[3][r];
    }
    sum = blockReduceSum4(sum);
    float mean[4] = { sum.x * (1.f / HD), sum.y * (1.f / HD),
                      sum.z * (1.f / HD), sum.w * (1.f / HD) };
    float4 sq;
    sq.x = 0.f; sq.y = 0.f; sq.z = 0.f; sq.w = 0.f;
    #pragma unroll
    for (int r = 0; r < 8; r++) {
        float d0 = acc[0][r] - mean[0]; sq.x += d0 * d0;
        float d1 = acc[1][r] - mean[1]; sq.y += d1 * d1;
        float d2 = acc[2][r] - mean[2]; sq.z += d2 * d2;
        float d3 = acc[3][r] - mean[3]; sq.w += d3 * d3;
    }
    sq = blockReduceSum4(sq);
    float rstd[4] = { rsqrtf(sq.x * (1.f / HD) + 1e-5f), rsqrtf(sq.y * (1.f / HD) + 1e-5f),
                      rsqrtf(sq.z * (1.f / HD) + 1e-5f), rsqrtf(sq.w * (1.f / HD) + 1e-5f) };

    #pragma unroll
    for (int j = 0; j < 4; j++) {
        float* op = out + ((long long)b * SS + s4 + j) * HD;
        #pragma unroll
        for (int r = 0; r < 8; r++) {
            int h = r * 256 + t;
            float yv = (acc[j][r] - mean[j]) * rstd[j] * g[h] + beta[h];
            float ge = 0.5f * yv * (1.f + erff(yv * 0.70710678118654752f));
            op[h] = cvt_tf32(ge);
        }
    }
}

// ---------------- launch ----------------------------------------------------
extern "C" void kernel_launch(void* const* d_in, const int* in_sizes, int n_in,
                              void* d_out, int out_size)
{
    const float* x      = (const float*)d_in[0];
    const float* Wq     = (const float*)d_in[1];
    const float* bq     = (const float*)d_in[2];
    const float* Wk     = (const float*)d_in[3];
    const float* bk     = (const float*)d_in[4];
    const float* Wv     = (const float*)d_in[5];
    const float* bv     = (const float*)d_in[6];
    const float* scale  = (const float*)d_in[7];
    const float* fc1_w  = (const float*)d_in[8];
    const float* fc1_b  = (const float*)d_in[9];
    const float* dw_w   = (const float*)d_in[10];
    const float* dw_b   = (const float*)d_in[11];
    const float* fc2_w  = (const float*)d_in[12];
    const float* fc2_b  = (const float*)d_in[13];
    const float* ln1_g  = (const float*)d_in[14];
    const float* ln1_b  = (const float*)d_in[15];
    const float* lnm_g  = (const float*)d_in[16];
    const float* lnm_b  = (const float*)d_in[17];
    float* out = (float*)d_out;

    void *pqkv, *pxr, *pkt, *penh, *pt, *pa, *pax, *pkv, *pkvp;
    void *pwqkv, *pbqkv, *pw1, *pw2, *pksum, *pz;
    void *pcpm, *pcps, *pcfm, *pcfa, *pcfb;
    cudaGetSymbolAddress(&pqkv, g_qkv);
    cudaGetSymbolAddress(&pxr,  g_xr);
    cudaGetSymbolAddress(&pkt,  g_kt);
    cudaGetSymbolAddress(&penh, g_enh);
    cudaGetSymbolAddress(&pt,   g_t);
    cudaGetSymbolAddress(&pa,   g_a);
    cudaGetSymbolAddress(&pax,  g_ax);
    cudaGetSymbolAddress(&pkv,  g_kv);
    cudaGetSymbolAddress(&pkvp, g_kvp);
    cudaGetSymbolAddress(&pwqkv,g_wqkv);
    cudaGetSymbolAddress(&pbqkv,g_bqkv);
    cudaGetSymbolAddress(&pw1,  g_w1);
    cudaGetSymbolAddress(&pw2,  g_w2);
    cudaGetSymbolAddress(&pksum,g_ksum);
    cudaGetSymbolAddress(&pz,   g_z);
    cudaGetSymbolAddress(&pcpm, g_cpm);
    cudaGetSymbolAddress(&pcps, g_cps);
    cudaGetSymbolAddress(&pcfm, g_cfm);
    cudaGetSymbolAddress(&pcfa, g_cfa);
    cudaGetSymbolAddress(&pcfb, g_cfb);

    cudaFuncSetAttribute(gemm_tc<0,false,true ,false>, cudaFuncAttributeMaxDynamicSharedMemorySize, SMEM_GEMM_BYTES);
    cudaFuncSetAttribute(gemm_tc<1,false,false,true >, cudaFuncAttributeMaxDynamicSharedMemorySize, SMEM_GEMM_BYTES);
    cudaFuncSetAttribute(gemm_tc<2,false,false,false>, cudaFuncAttributeMaxDynamicSharedMemorySize, SMEM_GEMM_BYTES);
    cudaFuncSetAttribute(gemm_tc<3,false,false,false>, cudaFuncAttributeMaxDynamicSharedMemorySize, SMEM_GEMM_BYTES);
    cudaFuncSetAttribute(gemm_tc<4,false,false,false>, cudaFuncAttributeMaxDynamicSharedMemorySize, SMEM_GEMM_BYTES);
    cudaFuncSetAttribute(softmax_row_k_t, cudaFuncAttributeMaxDynamicSharedMemorySize, SMEM_SRKT);

    const long long BS  = (long long)CC * SS;
    const long long KVS = (long long)CC * CC;
    float* fqkv = (float*)pqkv;
    float* fw   = (float*)pwqkv;

    // 0. weight + input prep (all pre-rounded -> no cvt in any GEMM mainloop)
    round_tf32_kernel<<<(CC*HD/4 + 255)/256, 256>>>(fc1_w, (float*)pw1, CC*HD/4);
    round_tf32_kernel<<<(HD*CC/4 + 255)/256, 256>>>(fc2_w, (float*)pw2, HD*CC/4);
    round_tf32_kernel<<<(CC*CC/4 + 255)/256, 256>>>(Wq, fw,             CC*CC/4);
    round_tf32_kernel<<<(CC*CC/4 + 255)/256, 256>>>(Wk, fw + CC*CC,     CC*CC/4);
    round_tf32_kernel<<<(CC*CC/4 + 255)/256, 256>>>(Wv, fw + 2*CC*CC,   CC*CC/4);
    round_tf32_kernel<<<(int)((NB*BS/4 + 255)/256), 256>>>(x, (float*)pxr, (int)(NB*BS/4));
    concat_bias<<<6, 256>>>(bq, bk, bv, (float*)pbqkv);

    // 1. merged qkv GEMM (rounded out: v is consumed raw by kv GEMM)
    gemm_tc<0,false,true ,false><<<dim3(SS/128, 1536/128, NB), 256, SMEM_GEMM_BYTES>>>(
        fw, (float*)pxr, fqkv, 1536, SS, CC, 0, BS, QKS, (float*)pbqkv, nullptr, 0, 0);

    // 2. k path: softmax + renorm + ksum, writing kT directly
    zero_ksum<<<4, 1024>>>((float*)pksum);
    softmax_row_k_t<<<NB*SS/32, 256, SMEM_SRKT>>>(fqkv + BS, scale, (float*)pksum, (float*)pkt);

    // 3. q path: col-softmax stats, combine, fused normalize+renorm^3+z
    colsm_partial<<<dim3(CC/32, NB, KCHUNK), dim3(32, 8)>>>(fqkv, (float*)pcpm, (float*)pcps);
    colsm_combine<<<(NB*CC + 255)/256, 256>>>((float*)pcpm, (float*)pcps, scale,
                                              (float*)pcfm, (float*)pcfa, (float*)pcfb);
    rownorm_pow3_z<<<NB*SS, 128>>>(fqkv, (float*)pcfm, (float*)pcfa, (float*)pcfb,
                                   (float*)pksum, (float*)pz);

    // 4. kv = kT @ v with 2-way split-K, then reduce + round
    gemm_tc<1,false,false,true ><<<dim3(CC/128, CC/128, NB*2), 256, SMEM_GEMM_BYTES>>>(
        (float*)pkt, fqkv + 2*BS, (float*)pkvp, CC, CC, SS, BS, QKS, KVS,
        nullptr, nullptr, 0, 0);
    reduce_kv<<<(NB*CC*CC/4 + 255)/256, 256>>>((float*)pkvp, (float*)pkv);

    // 5. enhanced = x^T + z * (q @ kv)
    gemm_tc<2,false,false,false><<<dim3(CC/128, SS/128, NB), 256, SMEM_GEMM_BYTES>>>(
        fqkv, (float*)pkv, (float*)penh, SS, CC, CC, QKS, KVS, BS,
        (float*)pz, x, SS, BS);

    // 6. t = LN(enhanced)
    layernorm512<<<NB*SS, 128>>>((float*)penh, (float*)pt, lnm_g, lnm_b);

    // 7. a = t @ w1 + fc1_b
    gemm_tc<3,false,false,false><<<dim3(HD/128, (NB*SS)/128, 1), 256, SMEM_GEMM_BYTES>>>(
        (float*)pt, (float*)pw1, (float*)pa, NB*SS, HD, CC, 0, 0, 0,
        fc1_b, nullptr, 0, 0);

    // 8. ax = gelu(LN(dwconv3x3(a) + dw_b + a))  [4-token tiles]
    dw_ln_gelu4<<<NB*SS/4, 256>>>((float*)pa, dw_w, dw_b, ln1_g, ln1_b, (float*)pax);

    // 9. out = enhanced + ax @ w2 + fc2_b
    gemm_tc<4,false,false,false><<<dim3(CC/128, (NB*SS)/128, 1), 256, SMEM_GEMM_BYTES>>>(
        (float*)pax, (float*)pw2, out, NB*SS, CC, HD, 0, 0, 0,
        fc2_b, (float*)penh, 0, 0);
}